// round 1
// baseline (speedup 1.0000x reference)
#include <cuda_runtime.h>

// Problem constants
#define NB  4
#define GRP 8
#define CI  256
#define CO  256
#define HH  32
#define WWD 32
#define HWP 1024
#define MM  4
#define DDIM 64

// Scratch (device globals; no runtime allocation allowed)
__device__ float g_q [NB*GRP*CO*HWP];
__device__ float g_k [NB*GRP*CO*HWP];
__device__ float g_v [NB*GRP*CO*HWP];
__device__ float g_av[NB*GRP*CO*HWP];
__device__ float g_y [NB*GRP*CI*HWP];
__device__ float g_t [NB*GRP*CI*HWP];
__device__ float g_h1[NB*GRP*CO*HWP];
__device__ float g_f [NB*GRP*CI*HWP];

// ---------------------------------------------------------------------------
// Batched grouped GEMM: C[bz][o][p] = sum_i W[g][o][i] * X[bz][i][p] (+bias)(+relu)
// O=256, I=256, P=1024, bz = n*8+g (32 batches). BM=BN=128, BK=8, 256 thr, 8x8 microtile.
// ---------------------------------------------------------------------------
__global__ __launch_bounds__(256) void gemm_kernel(
    const float* __restrict__ Wt, const float* __restrict__ X,
    const float* __restrict__ bias, float* __restrict__ C, int relu)
{
    int bz = blockIdx.z;
    int g  = bz & 7;
    const float* A = Wt + (size_t)g  * 256 * 256;
    const float* B = X  + (size_t)bz * 256 * 1024;
    float*      Cb = C  + (size_t)bz * 256 * 1024;
    int o0 = blockIdx.y * 128;
    int p0 = blockIdx.x * 128;

    __shared__ float As[8][128];
    __shared__ float Bs[8][128];

    int t  = threadIdx.x;
    int ar = t >> 1,  ac = (t & 1) << 2;   // A: row o (0..127), col chunk (0 or 4)
    int br = t >> 5,  bc = (t & 31) << 2;  // B: row k (0..7), col chunk
    int to = (t >> 4) << 3;                // out o offset 0..120
    int tp = (t & 15) << 3;                // out p offset 0..120

    float acc[8][8];
#pragma unroll
    for (int i = 0; i < 8; i++)
#pragma unroll
        for (int j = 0; j < 8; j++) acc[i][j] = 0.f;

    for (int k0 = 0; k0 < 256; k0 += 8) {
        float4 a4 = *(const float4*)(A + (size_t)(o0 + ar) * 256 + k0 + ac);
        float4 b4 = *(const float4*)(B + (size_t)(k0 + br) * 1024 + p0 + bc);
        __syncthreads();
        As[ac + 0][ar] = a4.x; As[ac + 1][ar] = a4.y;
        As[ac + 2][ar] = a4.z; As[ac + 3][ar] = a4.w;
        *(float4*)(&Bs[br][bc]) = b4;
        __syncthreads();
#pragma unroll
        for (int k = 0; k < 8; k++) {
            float a[8], b[8];
            *(float4*)(a)     = *(const float4*)(&As[k][to]);
            *(float4*)(a + 4) = *(const float4*)(&As[k][to + 4]);
            *(float4*)(b)     = *(const float4*)(&Bs[k][tp]);
            *(float4*)(b + 4) = *(const float4*)(&Bs[k][tp + 4]);
#pragma unroll
            for (int i = 0; i < 8; i++)
#pragma unroll
                for (int j = 0; j < 8; j++) acc[i][j] += a[i] * b[j];
        }
    }

#pragma unroll
    for (int i = 0; i < 8; i++) {
        int o = o0 + to + i;
        float bi = bias ? bias[g * 256 + o] : 0.f;
#pragma unroll
        for (int j0 = 0; j0 < 8; j0 += 4) {
            float4 o4;
            o4.x = acc[i][j0 + 0] + bi;
            o4.y = acc[i][j0 + 1] + bi;
            o4.z = acc[i][j0 + 2] + bi;
            o4.w = acc[i][j0 + 3] + bi;
            if (relu) {
                o4.x = fmaxf(o4.x, 0.f); o4.y = fmaxf(o4.y, 0.f);
                o4.z = fmaxf(o4.z, 0.f); o4.w = fmaxf(o4.w, 0.f);
            }
            *(float4*)(Cb + (size_t)o * 1024 + p0 + tp + j0) = o4;
        }
    }
}

// ---------------------------------------------------------------------------
// Windowed attention with relative embeddings.
// grid: (W/8=4, H=32, N*M=16), block 256 (8 warps; warp wi = pixel w0+wi).
// Dynamic smem layout (floats):
//   sk[3][10][e*64+d]  15360 | sv 15360 | sq[pix8][g*64+d] 4096 (reused as av)
//   srh[e<4][i][d] 768 | srw[e'][j][d] 768 | sat[warp][g][e][9] 4608
// ---------------------------------------------------------------------------
__global__ __launch_bounds__(256) void attn_kernel(
    const float* __restrict__ q, const float* __restrict__ k,
    const float* __restrict__ v, const float* __restrict__ hm,
    const float* __restrict__ wmm, float* __restrict__ outp)
{
    extern __shared__ float smem[];
    float* sk  = smem;            // 15360
    float* sv  = sk  + 15360;     // 15360
    float* sq  = sv  + 15360;     // 4096
    float* srh = sq  + 4096;      // 768
    float* srw = srh + 768;       // 768
    float* sat = srw + 768;       // 4608   -> total 40960 floats = 163840 B

    int t  = threadIdx.x;
    int w0 = blockIdx.x << 3;
    int h  = blockIdx.y;
    int nm = blockIdx.z;
    int n  = nm >> 2, m = nm & 3;

    // ---- load k/v halo (3 rows x 10 cols x 512 ch), zero OOB ----
    for (int idx = t; idx < 15360; idx += 256) {
        int c   = idx % 10;
        int red = idx / 10;            // ((r*8+e)*64+d)
        int d   = red & 63;
        int re  = red >> 6;
        int e   = re & 7, r = re >> 3;
        int hh2 = h + r - 1, ww2 = w0 + c - 1;
        float kv = 0.f, vv = 0.f;
        if (hh2 >= 0 && hh2 < 32 && ww2 >= 0 && ww2 < 32) {
            size_t gi = (((size_t)(n * 8 + e) * 256) + m * 64 + d) * 1024 + hh2 * 32 + ww2;
            kv = k[gi]; vv = v[gi];
        }
        int si = (r * 10 + c) * 512 + e * 64 + d;
        sk[si] = kv; sv[si] = vv;
    }
    // ---- load q for the 8 pixels ----
    for (int idx = t; idx < 4096; idx += 256) {
        int pix = idx & 7, gd = idx >> 3;
        size_t gi = (((size_t)(n * 8 + (gd >> 6)) * 256) + m * 64 + (gd & 63)) * 1024
                    + h * 32 + w0 + pix;
        sq[pix * 512 + gd] = q[gi];
    }
    // ---- load relative embeddings for this m ----
    for (int idx = t; idx < 768; idx += 256) {
        int d  = idx & 63;
        int ei = idx >> 6;             // e*3+i, e in 0..3
        int e  = ei / 3, i = ei % 3;
        srh[ei * 64 + d] = hm [((e * 256 + m * 64 + d) * 3) + i];
        srw[ei * 64 + d] = wmm[((e * 256 + m * 64 + d) * 3) + i];
    }
    __syncthreads();

    int wi = t >> 5, l = t & 31;
    int g  = l >> 2, e0 = l & 3;       // lane covers (g,e0) and (g,e0+4)
    const float* sqw = sq + wi * 512 + g * 64;
    int cc = wi + 1;

    // q . rel  (e0<4 -> hm varies over i; e0+4 -> wm varies over j)
    float qrA[3], qrB[3];
#pragma unroll
    for (int u = 0; u < 3; u++) {
        float a = 0.f, b = 0.f;
        const float* ra = srh + (e0 * 3 + u) * 64;
        const float* rb = srw + (e0 * 3 + u) * 64;
#pragma unroll
        for (int d = 0; d < 64; d += 4) {
            float4 qv = *(const float4*)(sqw + d);
            float4 r4 = *(const float4*)(ra + d);
            float4 s4 = *(const float4*)(rb + d);
            a += qv.x * r4.x + qv.y * r4.y + qv.z * r4.z + qv.w * r4.w;
            b += qv.x * s4.x + qv.y * s4.y + qv.z * s4.z + qv.w * s4.w;
        }
        qrA[u] = a; qrB[u] = b;
    }

    // scores over 9 neighbors for both e's
    float sA[9], sB[9];
#pragma unroll
    for (int u = 0; u < 9; u++) { sA[u] = 0.f; sB[u] = 0.f; }
#pragma unroll 4
    for (int dd = 0; dd < 64; dd += 4) {
        float4 qv = *(const float4*)(sqw + dd);
#pragma unroll
        for (int i = 0; i < 3; i++) {
#pragma unroll
            for (int j = 0; j < 3; j++) {
                const float* kp = sk + (i * 10 + cc - 1 + j) * 512 + e0 * 64 + dd;
                float4 k0v = *(const float4*)(kp);
                float4 k1v = *(const float4*)(kp + 256);   // e0+4
                sA[i * 3 + j] += qv.x * k0v.x + qv.y * k0v.y + qv.z * k0v.z + qv.w * k0v.w;
                sB[i * 3 + j] += qv.x * k1v.x + qv.y * k1v.y + qv.z * k1v.z + qv.w * k1v.w;
            }
        }
    }
#pragma unroll
    for (int u = 0; u < 9; u++) { sA[u] += qrA[u / 3]; sB[u] += qrB[u % 3]; }

    // softmax over 72 = (8e x 9nb), shared by the 4 lanes with equal g
    float mx = -1e30f;
#pragma unroll
    for (int u = 0; u < 9; u++) mx = fmaxf(mx, fmaxf(sA[u], sB[u]));
    mx = fmaxf(mx, __shfl_xor_sync(0xffffffffu, mx, 1));
    mx = fmaxf(mx, __shfl_xor_sync(0xffffffffu, mx, 2));
    float sum = 0.f;
#pragma unroll
    for (int u = 0; u < 9; u++) {
        sA[u] = __expf(sA[u] - mx);
        sB[u] = __expf(sB[u] - mx);
        sum += sA[u] + sB[u];
    }
    sum += __shfl_xor_sync(0xffffffffu, sum, 1);
    sum += __shfl_xor_sync(0xffffffffu, sum, 2);
    float inv = 1.f / sum;

    float* aw0 = sat + ((wi * 8 + g) * 8 + e0) * 9;
    float* aw1 = sat + ((wi * 8 + g) * 8 + e0 + 4) * 9;
#pragma unroll
    for (int u = 0; u < 9; u++) { aw0[u] = sA[u] * inv; aw1[u] = sB[u] * inv; }
    __syncwarp();

    // av[g][d] = sum_{e,i,j} attn * v ;  lane owns d=l and d=l+32; q region reused
    float* sav = sq + wi * 512;
#pragma unroll 1
    for (int gg = 0; gg < 8; gg++) {
        const float* aw = sat + (wi * 8 + gg) * 72;
        float a0 = 0.f, a1 = 0.f;
#pragma unroll
        for (int e = 0; e < 8; e++) {
#pragma unroll
            for (int i = 0; i < 3; i++) {
#pragma unroll
                for (int j = 0; j < 3; j++) {
                    float wgt = aw[e * 9 + i * 3 + j];
                    const float* vp = sv + (i * 10 + cc - 1 + j) * 512 + e * 64;
                    a0 += wgt * vp[l];
                    a1 += wgt * vp[l + 32];
                }
            }
        }
        sav[gg * 64 + l]      = a0;
        sav[gg * 64 + l + 32] = a1;
    }
    __syncthreads();

    // coalesced transpose write: out[n,g,m*64+d, h*32+w0 .. +7]
    for (int rr = t; rr < 512; rr += 256) {
        int g2 = rr >> 6, d2 = rr & 63;
        size_t ob = (((size_t)(n * 8 + g2) * 256) + m * 64 + d2) * 1024 + h * 32 + w0;
        float4 o0, o1;
        o0.x = sq[0 * 512 + rr]; o0.y = sq[1 * 512 + rr];
        o0.z = sq[2 * 512 + rr]; o0.w = sq[3 * 512 + rr];
        o1.x = sq[4 * 512 + rr]; o1.y = sq[5 * 512 + rr];
        o1.z = sq[6 * 512 + rr]; o1.w = sq[7 * 512 + rr];
        *(float4*)(outp + ob)     = o0;
        *(float4*)(outp + ob + 4) = o1;
    }
}

// ---------------------------------------------------------------------------
// Fused skip + LayerNorm over d=64. Writes T in flat (n, p, m, g, d) order,
// which IS the scrambled-reshape standard (n, g, 256, p) view.
// grid: (32 p-tiles, g*4+m, n), block 256.
// ---------------------------------------------------------------------------
__global__ __launch_bounds__(256) void ln_kernel(
    const float* __restrict__ X, const float* __restrict__ Y,
    const float* __restrict__ gamma, const float* __restrict__ beta,
    float* __restrict__ T)
{
    __shared__ float sx[64][33];
    int t  = threadIdx.x;
    int p0 = blockIdx.x << 5;
    int gm = blockIdx.y;
    int g  = gm >> 2, m = gm & 3;
    int n  = blockIdx.z;
    size_t base = (((size_t)(n * 8 + g) * 256) + m * 64) * 1024 + p0;
    int pp = t & 31;
#pragma unroll
    for (int pass = 0; pass < 8; pass++) {
        int d = (t >> 5) + pass * 8;
        sx[d][pp] = X[base + (size_t)d * 1024 + pp] + Y[base + (size_t)d * 1024 + pp];
    }
    __syncthreads();
    int c = t >> 3, sub = t & 7;
    float s1 = 0.f, s2 = 0.f;
#pragma unroll
    for (int u = 0; u < 8; u++) {
        float vv = sx[sub * 8 + u][c];
        s1 += vv; s2 += vv * vv;
    }
#pragma unroll
    for (int off = 1; off < 8; off <<= 1) {
        s1 += __shfl_xor_sync(0xffffffffu, s1, off);
        s2 += __shfl_xor_sync(0xffffffffu, s2, off);
    }
    float mu  = s1 * 0.015625f;
    float var = s2 * 0.015625f - mu * mu;      // biased var (matches ref)
    float inv = rsqrtf(var + 1e-5f);
    float* op = T + ((((size_t)n * 1024 + p0 + c) * 4 + m) * 8 + g) * 64;
#pragma unroll
    for (int u = 0; u < 8; u++) {
        int d = sub * 8 + u;
        op[d] = (sx[d][c] - mu) * inv * gamma[d] + beta[d];
    }
}

// ---------------------------------------------------------------------------
extern "C" void kernel_launch(void* const* d_in, const int* in_sizes, int n_in,
                              void* d_out, int out_size)
{
    (void)in_sizes; (void)n_in; (void)out_size;
    const float* x     = (const float*)d_in[0];
    const float* wq    = (const float*)d_in[1];
    const float* wk    = (const float*)d_in[2];
    const float* wv    = (const float*)d_in[3];
    const float* hm    = (const float*)d_in[4];
    const float* wm    = (const float*)d_in[5];
    const float* wconv = (const float*)d_in[6];
    const float* bconv = (const float*)d_in[7];
    const float* wf1   = (const float*)d_in[8];
    const float* bf1   = (const float*)d_in[9];
    const float* wf2   = (const float*)d_in[10];
    const float* bf2   = (const float*)d_in[11];
    const float* g1    = (const float*)d_in[12];
    const float* b1    = (const float*)d_in[13];
    const float* g2    = (const float*)d_in[14];
    const float* b2    = (const float*)d_in[15];

    float *q, *k, *v, *av, *y, *tb, *h1, *f;
    cudaGetSymbolAddress((void**)&q,  g_q);
    cudaGetSymbolAddress((void**)&k,  g_k);
    cudaGetSymbolAddress((void**)&v,  g_v);
    cudaGetSymbolAddress((void**)&av, g_av);
    cudaGetSymbolAddress((void**)&y,  g_y);
    cudaGetSymbolAddress((void**)&tb, g_t);
    cudaGetSymbolAddress((void**)&h1, g_h1);
    cudaGetSymbolAddress((void**)&f,  g_f);

    cudaFuncSetAttribute(attn_kernel,
                         cudaFuncAttributeMaxDynamicSharedMemorySize, 163840);

    dim3 gdim(8, 2, 32);   // P/128, O/128, n*g
    gemm_kernel<<<gdim, 256>>>(wq, x, nullptr, q, 0);
    gemm_kernel<<<gdim, 256>>>(wk, x, nullptr, k, 0);
    gemm_kernel<<<gdim, 256>>>(wv, x, nullptr, v, 0);

    attn_kernel<<<dim3(4, 32, 16), 256, 163840>>>(q, k, v, hm, wm, av);

    gemm_kernel<<<gdim, 256>>>(wconv, av, bconv, y, 0);
    ln_kernel<<<dim3(32, 32, 4), 256>>>(x, y, g1, b1, tb);
    gemm_kernel<<<gdim, 256>>>(wf1, tb, bf1, h1, 1);
    gemm_kernel<<<gdim, 256>>>(wf2, h1, bf2, f, 0);
    ln_kernel<<<dim3(32, 32, 4), 256>>>(tb, f, g2, b2, (float*)d_out);
}